// round 4
// baseline (speedup 1.0000x reference)
#include <cuda_runtime.h>
#include <math.h>
#include <stdint.h>

#define Dm    1024
#define HEADS 16
#define HDIM  64
#define MLPD  4096
#define BATCH 2
#define SEQ   2048
#define ROWS  (BATCH*SEQ)   // 4096

// ---------------- scratch (no allocation allowed) ----------------
__device__ float g_h  [(size_t)ROWS*Dm];      // 16 MB
__device__ float g_qkv[(size_t)ROWS*3*Dm];    // 48 MB
__device__ float g_o  [(size_t)ROWS*Dm];      // 16 MB
__device__ float g_x1 [(size_t)ROWS*Dm];      // 16 MB
__device__ float g_m  [(size_t)ROWS*Dm];      // 16 MB
__device__ float g_ma [(size_t)ROWS*MLPD];    // 64 MB

// Device-side buffer table: resolved ON DEVICE so kernel_launch makes no
// runtime-API calls at all (pure kernel launches -> trivially graph-capturable).
__device__ float* const g_ptrs[6] = { g_h, g_qkv, g_o, g_x1, g_m, g_ma };

__device__ __forceinline__ const float* resolve_c(int id, const float* ext) {
    return id < 0 ? ext : (const float*)g_ptrs[id];
}
__device__ __forceinline__ float* resolve_m(int id, float* ext) {
    return id < 0 ? ext : g_ptrs[id];
}

// ---------------- LayerNorm ----------------
__global__ void ln_kernel(int in_id, const float* __restrict__ x_ext,
                          const float* __restrict__ g, const float* __restrict__ b,
                          int out_id) {
    const float* x = resolve_c(in_id, x_ext);
    float* out = g_ptrs[out_id];
    int row = blockIdx.x;
    int tid = threadIdx.x;            // 256 threads, 4 elems each
    const float4* xr = (const float4*)(x + (size_t)row * Dm);
    float4 v = xr[tid];
    float s  = v.x + v.y + v.z + v.w;
    float ss = v.x*v.x + v.y*v.y + v.z*v.z + v.w*v.w;
    #pragma unroll
    for (int o = 16; o > 0; o >>= 1) {
        s  += __shfl_xor_sync(0xffffffffu, s,  o);
        ss += __shfl_xor_sync(0xffffffffu, ss, o);
    }
    __shared__ float sh_s[8], sh_ss[8];
    int w = tid >> 5, lane = tid & 31;
    if (lane == 0) { sh_s[w] = s; sh_ss[w] = ss; }
    __syncthreads();
    s = 0.f; ss = 0.f;
    #pragma unroll
    for (int i = 0; i < 8; i++) { s += sh_s[i]; ss += sh_ss[i]; }
    float mu  = s * (1.0f / Dm);
    float var = ss * (1.0f / Dm) - mu * mu;
    float r   = rsqrtf(var + 1e-5f);
    float4 gg = ((const float4*)g)[tid];
    float4 bb = ((const float4*)b)[tid];
    float4 o4;
    o4.x = (v.x - mu) * r * gg.x + bb.x;
    o4.y = (v.y - mu) * r * gg.y + bb.y;
    o4.z = (v.z - mu) * r * gg.z + bb.z;
    o4.w = (v.w - mu) * r * gg.w + bb.w;
    ((float4*)(out + (size_t)row * Dm))[tid] = o4;
}

// ---------------- GELU (exact, erf-based) ----------------
__device__ __forceinline__ float gelu_f(float x) {
    return 0.5f * x * (1.0f + erff(x * 0.70710678118654752f));
}

// ---------------- tiled SGEMM with fused epilogue ----------------
// EPI: 0 = bias, 1 = bias + residual, 2 = bias + GELU
template<int EPI>
__global__ __launch_bounds__(256, 2)
void sgemm(int a_id, const float* __restrict__ B,
           const float* __restrict__ bias,
           int res_id, const float* __restrict__ res_ext,
           int c_id, float* __restrict__ c_ext,
           int M, int N, int K) {
    const float* A = (const float*)g_ptrs[a_id];
    const float* res = (EPI == 1) ? resolve_c(res_id, res_ext) : nullptr;
    float* C = resolve_m(c_id, c_ext);

    constexpr int BM = 128, BN = 128, BK = 16;
    __shared__ float As[BK][BM];
    __shared__ float Bs[BK][BN];
    int tid  = threadIdx.x;
    int row0 = blockIdx.y * BM;
    int col0 = blockIdx.x * BN;
    int tx = tid & 15, ty = tid >> 4;

    float acc[8][8];
    #pragma unroll
    for (int i = 0; i < 8; i++)
        #pragma unroll
        for (int j = 0; j < 8; j++) acc[i][j] = 0.f;

    for (int k0 = 0; k0 < K; k0 += BK) {
        // stage A (transposed into As[k][m])
        #pragma unroll
        for (int l = 0; l < 2; l++) {
            int i = tid + l * 256;            // 0..511
            int r = i >> 2, c = (i & 3) * 4;  // r: 0..127, c: 0/4/8/12
            float4 a = *(const float4*)(A + (size_t)(row0 + r) * K + k0 + c);
            As[c + 0][r] = a.x; As[c + 1][r] = a.y;
            As[c + 2][r] = a.z; As[c + 3][r] = a.w;
        }
        // stage B
        #pragma unroll
        for (int l = 0; l < 2; l++) {
            int i = tid + l * 256;            // 0..511
            int r = i >> 5, c = (i & 31) * 4; // r: 0..15, c: 0..124
            *(float4*)&Bs[r][c] = *(const float4*)(B + (size_t)(k0 + r) * N + col0 + c);
        }
        __syncthreads();
        #pragma unroll
        for (int kk = 0; kk < BK; kk++) {
            float4 a0 = *(const float4*)&As[kk][ty * 8];
            float4 a1 = *(const float4*)&As[kk][ty * 8 + 4];
            float4 b0 = *(const float4*)&Bs[kk][tx * 8];
            float4 b1 = *(const float4*)&Bs[kk][tx * 8 + 4];
            float af[8] = {a0.x, a0.y, a0.z, a0.w, a1.x, a1.y, a1.z, a1.w};
            float bf[8] = {b0.x, b0.y, b0.z, b0.w, b1.x, b1.y, b1.z, b1.w};
            #pragma unroll
            for (int i = 0; i < 8; i++)
                #pragma unroll
                for (int j = 0; j < 8; j++)
                    acc[i][j] = fmaf(af[i], bf[j], acc[i][j]);
        }
        __syncthreads();
    }

    // epilogue
    #pragma unroll
    for (int i = 0; i < 8; i++) {
        int r = row0 + ty * 8 + i;
        #pragma unroll
        for (int jj = 0; jj < 2; jj++) {
            int c = col0 + tx * 8 + jj * 4;
            float4 b4 = *(const float4*)(bias + c);
            float4 v;
            v.x = acc[i][jj*4+0] + b4.x;
            v.y = acc[i][jj*4+1] + b4.y;
            v.z = acc[i][jj*4+2] + b4.z;
            v.w = acc[i][jj*4+3] + b4.w;
            if (EPI == 1) {
                float4 r4 = *(const float4*)(res + (size_t)r * N + c);
                v.x += r4.x; v.y += r4.y; v.z += r4.z; v.w += r4.w;
            }
            if (EPI == 2) {
                v.x = gelu_f(v.x); v.y = gelu_f(v.y);
                v.z = gelu_f(v.z); v.w = gelu_f(v.w);
            }
            *(float4*)(C + (size_t)r * N + c) = v;
        }
    }
}

// ---------------- flash-style attention (fp32) ----------------
// grid: (SEQ/128, BATCH*HEADS); block: 128 threads, one query row each.
__global__ __launch_bounds__(128)
void attn_kernel() {
    const float* qkv = g_qkv;
    float* o_out = g_o;
    const int bh = blockIdx.y;
    const int b  = bh / HEADS;
    const int h  = bh % HEADS;
    const int qi = blockIdx.x * 128 + threadIdx.x;
    const int tid = threadIdx.x;
    const float scale = 0.125f;   // 1/sqrt(64)

    const float* base = qkv + (size_t)b * SEQ * (3 * Dm);

    float4 qreg[16];
    {
        const float4* qp = (const float4*)(base + (size_t)qi * (3 * Dm) + h * HDIM);
        #pragma unroll
        for (int i = 0; i < 16; i++) qreg[i] = qp[i];
    }

    float4 oacc[16];
    #pragma unroll
    for (int i = 0; i < 16; i++) oacc[i] = make_float4(0.f, 0.f, 0.f, 0.f);
    float mx = -1e30f, l = 0.f;

    __shared__ float4 Ks[64][16];
    __shared__ float4 Vs[64][16];

    for (int kt = 0; kt < SEQ; kt += 64) {
        __syncthreads();
        #pragma unroll
        for (int i = tid; i < 1024; i += 128) {
            int r = i >> 4, c = i & 15;
            const float* krow = base + (size_t)(kt + r) * (3 * Dm) + Dm + h * HDIM;
            Ks[r][c] = ((const float4*)krow)[c];
            Vs[r][c] = ((const float4*)(krow + Dm))[c];
        }
        __syncthreads();
        for (int j = 0; j < 64; j++) {
            float s = 0.f;
            #pragma unroll
            for (int c = 0; c < 16; c++) {
                float4 kv = Ks[j][c];
                float4 qv = qreg[c];
                s = fmaf(qv.x, kv.x, s);
                s = fmaf(qv.y, kv.y, s);
                s = fmaf(qv.z, kv.z, s);
                s = fmaf(qv.w, kv.w, s);
            }
            s *= scale;
            if (s > mx) {
                float corr = __expf(mx - s);
                l *= corr;
                #pragma unroll
                for (int c = 0; c < 16; c++) {
                    oacc[c].x *= corr; oacc[c].y *= corr;
                    oacc[c].z *= corr; oacc[c].w *= corr;
                }
                mx = s;
            }
            float p = __expf(s - mx);
            l += p;
            #pragma unroll
            for (int c = 0; c < 16; c++) {
                float4 vv = Vs[j][c];
                oacc[c].x = fmaf(p, vv.x, oacc[c].x);
                oacc[c].y = fmaf(p, vv.y, oacc[c].y);
                oacc[c].z = fmaf(p, vv.z, oacc[c].z);
                oacc[c].w = fmaf(p, vv.w, oacc[c].w);
            }
        }
    }

    float inv = 1.0f / l;
    float4* op = (float4*)(o_out + (size_t)(b * SEQ + qi) * Dm + h * HDIM);
    #pragma unroll
    for (int c = 0; c < 16; c++) {
        float4 v = oacc[c];
        v.x *= inv; v.y *= inv; v.z *= inv; v.w *= inv;
        op[c] = v;
    }
}

// ---------------- launch ----------------
// Buffer ids: 0=g_h 1=g_qkv 2=g_o 3=g_x1 4=g_m 5=g_ma ; -1 = external ptr
extern "C" void kernel_launch(void* const* d_in, const int* in_sizes, int n_in,
                              void* d_out, int out_size) {
    const float* x      = (const float*)d_in[0];
    const float* ln1_g  = (const float*)d_in[1];
    const float* ln1_b  = (const float*)d_in[2];
    const float* lnm_g  = (const float*)d_in[3];
    const float* lnm_b  = (const float*)d_in[4];
    const float* qkv_w  = (const float*)d_in[5];
    const float* qkv_b  = (const float*)d_in[6];
    const float* proj_w = (const float*)d_in[7];
    const float* proj_b = (const float*)d_in[8];
    const float* fc1_w  = (const float*)d_in[9];
    const float* fc1_b  = (const float*)d_in[10];
    const float* fc2_w  = (const float*)d_in[11];
    const float* fc2_b  = (const float*)d_in[12];
    float* out = (float*)d_out;

    // 1. LN1: g_h = LN(x)
    ln_kernel<<<ROWS, 256>>>(-1, x, ln1_g, ln1_b, 0);
    // 2. QKV: g_qkv = g_h @ qkv_w + qkv_b   [4096, 3072]
    sgemm<0><<<dim3(3 * Dm / 128, ROWS / 128), 256>>>(0, qkv_w, qkv_b,
                                                      -1, nullptr, 1, nullptr,
                                                      ROWS, 3 * Dm, Dm);
    // 3. attention: g_o                      [4096, 1024]
    attn_kernel<<<dim3(SEQ / 128, BATCH * HEADS), 128>>>();
    // 4. g_x1 = x + g_o @ proj_w + proj_b
    sgemm<1><<<dim3(Dm / 128, ROWS / 128), 256>>>(2, proj_w, proj_b,
                                                  -1, x, 3, nullptr,
                                                  ROWS, Dm, Dm);
    // 5. LNm: g_m = LN(g_x1)
    ln_kernel<<<ROWS, 256>>>(3, nullptr, lnm_g, lnm_b, 4);
    // 6. g_ma = gelu(g_m @ fc1_w + fc1_b)    [4096, 4096]
    sgemm<2><<<dim3(MLPD / 128, ROWS / 128), 256>>>(4, fc1_w, fc1_b,
                                                    -1, nullptr, 5, nullptr,
                                                    ROWS, MLPD, Dm);
    // 7. out = g_x1 + g_ma @ fc2_w + fc2_b   [4096, 1024]
    sgemm<1><<<dim3(Dm / 128, ROWS / 128), 256>>>(5, fc2_w, fc2_b,
                                                  3, nullptr, -1, out,
                                                  ROWS, Dm, MLPD);
}

// round 6
// speedup vs baseline: 1.5940x; 1.5940x over previous
#include <cuda_runtime.h>
#include <math.h>
#include <stdint.h>

#define Dm    1024
#define HEADS 16
#define HDIM  64
#define MLPD  4096
#define BATCH 2
#define SEQ   2048
#define ROWS  (BATCH*SEQ)   // 4096

// ---------------- scratch (no allocation allowed) ----------------
__device__ float g_h  [(size_t)ROWS*Dm];
__device__ float g_qkv[(size_t)ROWS*3*Dm];
__device__ float g_o  [(size_t)ROWS*Dm];
__device__ float g_x1 [(size_t)ROWS*Dm];
__device__ float g_m  [(size_t)ROWS*Dm];
__device__ float g_ma [(size_t)ROWS*MLPD];
__device__ float g_wt [(size_t)4*1024*1024];   // transposed weight staging [N][K]

__device__ float* const g_ptrs[7] = { g_h, g_qkv, g_o, g_x1, g_m, g_ma, g_wt };

__device__ __forceinline__ const float* resolve_c(int id, const float* ext) {
    return id < 0 ? ext : (const float*)g_ptrs[id];
}
__device__ __forceinline__ float* resolve_m(int id, float* ext) {
    return id < 0 ? ext : g_ptrs[id];
}

__device__ __forceinline__ uint32_t to_tf32(float f) {
    uint32_t r;
    asm("cvt.rna.tf32.f32 %0, %1;" : "=r"(r) : "f"(f));
    return r;
}

// ---------------- LayerNorm ----------------
__global__ void ln_kernel(int in_id, const float* __restrict__ x_ext,
                          const float* __restrict__ g, const float* __restrict__ b,
                          int out_id) {
    const float* x = resolve_c(in_id, x_ext);
    float* out = g_ptrs[out_id];
    int row = blockIdx.x;
    int tid = threadIdx.x;
    const float4* xr = (const float4*)(x + (size_t)row * Dm);
    float4 v = xr[tid];
    float s  = v.x + v.y + v.z + v.w;
    float ss = v.x*v.x + v.y*v.y + v.z*v.z + v.w*v.w;
    #pragma unroll
    for (int o = 16; o > 0; o >>= 1) {
        s  += __shfl_xor_sync(0xffffffffu, s,  o);
        ss += __shfl_xor_sync(0xffffffffu, ss, o);
    }
    __shared__ float sh_s[8], sh_ss[8];
    int w = tid >> 5, lane = tid & 31;
    if (lane == 0) { sh_s[w] = s; sh_ss[w] = ss; }
    __syncthreads();
    s = 0.f; ss = 0.f;
    #pragma unroll
    for (int i = 0; i < 8; i++) { s += sh_s[i]; ss += sh_ss[i]; }
    float mu  = s * (1.0f / Dm);
    float var = ss * (1.0f / Dm) - mu * mu;
    float r   = rsqrtf(var + 1e-5f);
    float4 gg = ((const float4*)g)[tid];
    float4 bb = ((const float4*)b)[tid];
    float4 o4;
    o4.x = (v.x - mu) * r * gg.x + bb.x;
    o4.y = (v.y - mu) * r * gg.y + bb.y;
    o4.z = (v.z - mu) * r * gg.z + bb.z;
    o4.w = (v.w - mu) * r * gg.w + bb.w;
    ((float4*)(out + (size_t)row * Dm))[tid] = o4;
}

// ---------------- weight transpose: W[K][N] -> g_wt[N][K] ----------------
__global__ void transpose_w(const float* __restrict__ W, int K, int N) {
    __shared__ float t[32][33];
    int bx = blockIdx.x * 32;   // n
    int by = blockIdx.y * 32;   // k
    int x = threadIdx.x, y = threadIdx.y;   // 32 x 8
    #pragma unroll
    for (int j = 0; j < 4; j++)
        t[y + 8*j][x] = W[(size_t)(by + y + 8*j) * N + bx + x];
    __syncthreads();
    #pragma unroll
    for (int j = 0; j < 4; j++)
        g_wt[(size_t)(bx + y + 8*j) * K + by + x] = t[x][y + 8*j];
}

// ---------------- GELU (exact) ----------------
__device__ __forceinline__ float gelu_f(float x) {
    return 0.5f * x * (1.0f + erff(x * 0.70710678118654752f));
}

// ---------------- tf32 mma.sync GEMM ----------------
// C[M,N] = A[M,K] @ W[K,N] (+bias/res/gelu), W supplied transposed in g_wt[N][K].
// CTA: 128x128, 256 threads (8 warps in 2x4), BK=32.
#define PAD 36

__device__ __forceinline__ void mma_tf32(float* d, const uint32_t* a, const uint32_t* b) {
    asm volatile(
        "mma.sync.aligned.m16n8k8.row.col.f32.tf32.tf32.f32 "
        "{%0,%1,%2,%3}, {%4,%5,%6,%7}, {%8,%9}, {%0,%1,%2,%3};"
        : "+f"(d[0]), "+f"(d[1]), "+f"(d[2]), "+f"(d[3])
        : "r"(a[0]), "r"(a[1]), "r"(a[2]), "r"(a[3]), "r"(b[0]), "r"(b[1]));
}

template<int EPI>
__global__ __launch_bounds__(256)
void gemm_mma(int a_id, const float* __restrict__ bias,
              int res_id, const float* __restrict__ res_ext,
              int c_id, float* __restrict__ c_ext,
              int M, int N, int K) {
    const float* A  = (const float*)g_ptrs[a_id];
    const float* Bw = g_wt;
    const float* res = (EPI == 1) ? resolve_c(res_id, res_ext) : nullptr;
    float* C = resolve_m(c_id, c_ext);

    __shared__ uint32_t As[128 * PAD];
    __shared__ uint32_t Bs[128 * PAD];

    const int tid  = threadIdx.x;
    const int wid  = tid >> 5, lane = tid & 31;
    const int row0 = blockIdx.y * 128;
    const int col0 = blockIdx.x * 128;
    const int mw   = (wid & 1) * 64;   // warp row offset
    const int nw   = (wid >> 1) * 32;  // warp col offset
    const int lr   = tid >> 1;         // loader row 0..127
    const int lc   = (tid & 1) * 16;   // loader col 0 or 16

    float acc[4][4][4];
    #pragma unroll
    for (int i = 0; i < 4; i++)
        #pragma unroll
        for (int j = 0; j < 4; j++)
            #pragma unroll
            for (int e = 0; e < 4; e++) acc[i][j][e] = 0.f;

    const int r4 = lane >> 2, c4 = lane & 3;

    for (int k0 = 0; k0 < K; k0 += 32) {
        // stage A and B tiles (converted to tf32)
        const float4* pa = (const float4*)(A  + (size_t)(row0 + lr) * K + k0 + lc);
        const float4* pb = (const float4*)(Bw + (size_t)(col0 + lr) * K + k0 + lc);
        #pragma unroll
        for (int j = 0; j < 4; j++) {
            float4 va = pa[j];
            uint4 ua = { to_tf32(va.x), to_tf32(va.y), to_tf32(va.z), to_tf32(va.w) };
            *(uint4*)&As[lr * PAD + lc + 4*j] = ua;
            float4 vb = pb[j];
            uint4 ub = { to_tf32(vb.x), to_tf32(vb.y), to_tf32(vb.z), to_tf32(vb.w) };
            *(uint4*)&Bs[lr * PAD + lc + 4*j] = ub;
        }
        __syncthreads();

        #pragma unroll
        for (int ks = 0; ks < 4; ks++) {
            const int kb = ks * 8;
            uint32_t afr[4][4];
            #pragma unroll
            for (int mt = 0; mt < 4; mt++) {
                int m = mw + mt * 16;
                afr[mt][0] = As[(m + r4)     * PAD + kb + c4];
                afr[mt][1] = As[(m + r4 + 8) * PAD + kb + c4];
                afr[mt][2] = As[(m + r4)     * PAD + kb + c4 + 4];
                afr[mt][3] = As[(m + r4 + 8) * PAD + kb + c4 + 4];
            }
            uint32_t bfr[4][2];
            #pragma unroll
            for (int nt = 0; nt < 4; nt++) {
                int n = nw + nt * 8;
                bfr[nt][0] = Bs[(n + r4) * PAD + kb + c4];
                bfr[nt][1] = Bs[(n + r4) * PAD + kb + c4 + 4];
            }
            #pragma unroll
            for (int mt = 0; mt < 4; mt++)
                #pragma unroll
                for (int nt = 0; nt < 4; nt++)
                    mma_tf32(acc[mt][nt], afr[mt], bfr[nt]);
        }
        __syncthreads();
    }

    // ---- epilogue ----
    #pragma unroll
    for (int mt = 0; mt < 4; mt++) {
        #pragma unroll
        for (int nt = 0; nt < 4; nt++) {
            int gm = row0 + mw + mt * 16 + r4;
            int gn = col0 + nw + nt * 8 + 2 * c4;
            float2 bi = *(const float2*)(bias + gn);
            #pragma unroll
            for (int half = 0; half < 2; half++) {
                int rr = gm + half * 8;
                float2 v;
                v.x = acc[mt][nt][half*2 + 0] + bi.x;
                v.y = acc[mt][nt][half*2 + 1] + bi.y;
                if (EPI == 1) {
                    float2 r2 = *(const float2*)(res + (size_t)rr * N + gn);
                    v.x += r2.x; v.y += r2.y;
                }
                if (EPI == 2) { v.x = gelu_f(v.x); v.y = gelu_f(v.y); }
                *(float2*)(C + (size_t)rr * N + gn) = v;
            }
        }
    }
}

// ---------------- flash-style attention (fp32, unchanged) ----------------
__global__ __launch_bounds__(128)
void attn_kernel() {
    const float* qkv = g_qkv;
    float* o_out = g_o;
    const int bh = blockIdx.y;
    const int b  = bh / HEADS;
    const int h  = bh % HEADS;
    const int qi = blockIdx.x * 128 + threadIdx.x;
    const int tid = threadIdx.x;
    const float scale = 0.125f;

    const float* base = qkv + (size_t)b * SEQ * (3 * Dm);

    float4 qreg[16];
    {
        const float4* qp = (const float4*)(base + (size_t)qi * (3 * Dm) + h * HDIM);
        #pragma unroll
        for (int i = 0; i < 16; i++) qreg[i] = qp[i];
    }

    float4 oacc[16];
    #pragma unroll
    for (int i = 0; i < 16; i++) oacc[i] = make_float4(0.f, 0.f, 0.f, 0.f);
    float mx = -1e30f, l = 0.f;

    __shared__ float4 Ks[64][16];
    __shared__ float4 Vs[64][16];

    for (int kt = 0; kt < SEQ; kt += 64) {
        __syncthreads();
        #pragma unroll
        for (int i = tid; i < 1024; i += 128) {
            int r = i >> 4, c = i & 15;
            const float* krow = base + (size_t)(kt + r) * (3 * Dm) + Dm + h * HDIM;
            Ks[r][c] = ((const float4*)krow)[c];
            Vs[r][c] = ((const float4*)(krow + Dm))[c];
        }
        __syncthreads();
        for (int j = 0; j < 64; j++) {
            float s = 0.f;
            #pragma unroll
            for (int c = 0; c < 16; c++) {
                float4 kv = Ks[j][c];
                float4 qv = qreg[c];
                s = fmaf(qv.x, kv.x, s);
                s = fmaf(qv.y, kv.y, s);
                s = fmaf(qv.z, kv.z, s);
                s = fmaf(qv.w, kv.w, s);
            }
            s *= scale;
            if (s > mx) {
                float corr = __expf(mx - s);
                l *= corr;
                #pragma unroll
                for (int c = 0; c < 16; c++) {
                    oacc[c].x *= corr; oacc[c].y *= corr;
                    oacc[c].z *= corr; oacc[c].w *= corr;
                }
                mx = s;
            }
            float p = __expf(s - mx);
            l += p;
            #pragma unroll
            for (int c = 0; c < 16; c++) {
                float4 vv = Vs[j][c];
                oacc[c].x = fmaf(p, vv.x, oacc[c].x);
                oacc[c].y = fmaf(p, vv.y, oacc[c].y);
                oacc[c].z = fmaf(p, vv.z, oacc[c].z);
                oacc[c].w = fmaf(p, vv.w, oacc[c].w);
            }
        }
    }

    float inv = 1.0f / l;
    float4* op = (float4*)(o_out + (size_t)(b * SEQ + qi) * Dm + h * HDIM);
    #pragma unroll
    for (int c = 0; c < 16; c++) {
        float4 v = oacc[c];
        v.x *= inv; v.y *= inv; v.z *= inv; v.w *= inv;
        op[c] = v;
    }
}

// ---------------- launch ----------------
// Buffer ids: 0=g_h 1=g_qkv 2=g_o 3=g_x1 4=g_m 5=g_ma 6=g_wt ; -1 = external
extern "C" void kernel_launch(void* const* d_in, const int* in_sizes, int n_in,
                              void* d_out, int out_size) {
    const float* x      = (const float*)d_in[0];
    const float* ln1_g  = (const float*)d_in[1];
    const float* ln1_b  = (const float*)d_in[2];
    const float* lnm_g  = (const float*)d_in[3];
    const float* lnm_b  = (const float*)d_in[4];
    const float* qkv_w  = (const float*)d_in[5];
    const float* qkv_b  = (const float*)d_in[6];
    const float* proj_w = (const float*)d_in[7];
    const float* proj_b = (const float*)d_in[8];
    const float* fc1_w  = (const float*)d_in[9];
    const float* fc1_b  = (const float*)d_in[10];
    const float* fc2_w  = (const float*)d_in[11];
    const float* fc2_b  = (const float*)d_in[12];
    float* out = (float*)d_out;

    // 1. LN1: g_h = LN(x)
    ln_kernel<<<ROWS, 256>>>(-1, x, ln1_g, ln1_b, 0);
    // 2. QKV: g_qkv = g_h @ qkv_w + qkv_b
    transpose_w<<<dim3(3 * Dm / 32, Dm / 32), dim3(32, 8)>>>(qkv_w, Dm, 3 * Dm);
    gemm_mma<0><<<dim3(3 * Dm / 128, ROWS / 128), 256>>>(
        0, qkv_b, -1, nullptr, 1, nullptr, ROWS, 3 * Dm, Dm);
    // 3. attention
    attn_kernel<<<dim3(SEQ / 128, BATCH * HEADS), 128>>>();
    // 4. g_x1 = x + g_o @ proj_w + proj_b
    transpose_w<<<dim3(Dm / 32, Dm / 32), dim3(32, 8)>>>(proj_w, Dm, Dm);
    gemm_mma<1><<<dim3(Dm / 128, ROWS / 128), 256>>>(
        2, proj_b, -1, x, 3, nullptr, ROWS, Dm, Dm);
    // 5. LNm: g_m = LN(g_x1)
    ln_kernel<<<ROWS, 256>>>(3, nullptr, lnm_g, lnm_b, 4);
    // 6. g_ma = gelu(g_m @ fc1_w + fc1_b)
    transpose_w<<<dim3(MLPD / 32, Dm / 32), dim3(32, 8)>>>(fc1_w, Dm, MLPD);
    gemm_mma<2><<<dim3(MLPD / 128, ROWS / 128), 256>>>(
        4, fc1_b, -1, nullptr, 5, nullptr, ROWS, MLPD, Dm);
    // 7. out = g_x1 + g_ma @ fc2_w + fc2_b
    transpose_w<<<dim3(Dm / 32, MLPD / 32), dim3(32, 8)>>>(fc2_w, MLPD, Dm);
    gemm_mma<1><<<dim3(Dm / 128, ROWS / 128), 256>>>(
        5, fc2_b, 3, nullptr, -1, out, ROWS, Dm, MLPD);
}

// round 7
// speedup vs baseline: 2.4048x; 1.5087x over previous
#include <cuda_runtime.h>
#include <math.h>
#include <stdint.h>

#define Dm    1024
#define HEADS 16
#define HDIM  64
#define MLPD  4096
#define BATCH 2
#define SEQ   2048
#define ROWS  (BATCH*SEQ)   // 4096

// ---------------- scratch (no allocation allowed) ----------------
__device__ float g_h  [(size_t)ROWS*Dm];
__device__ float g_qkv[(size_t)ROWS*3*Dm];
__device__ float g_o  [(size_t)ROWS*Dm];
__device__ float g_x1 [(size_t)ROWS*Dm];
__device__ float g_m  [(size_t)ROWS*Dm];
__device__ float g_ma [(size_t)ROWS*MLPD];
__device__ float g_wt [(size_t)4*1024*1024];   // transposed weight staging [N][K]

__device__ float* const g_ptrs[7] = { g_h, g_qkv, g_o, g_x1, g_m, g_ma, g_wt };

__device__ __forceinline__ const float* resolve_c(int id, const float* ext) {
    return id < 0 ? ext : (const float*)g_ptrs[id];
}
__device__ __forceinline__ float* resolve_m(int id, float* ext) {
    return id < 0 ? ext : g_ptrs[id];
}

__device__ __forceinline__ uint32_t to_tf32(float f) {
    uint32_t r;
    asm("cvt.rna.tf32.f32 %0, %1;" : "=r"(r) : "f"(f));
    return r;
}

__device__ __forceinline__ void mma_tf32(float* d, const uint32_t* a, const uint32_t* b) {
    asm volatile(
        "mma.sync.aligned.m16n8k8.row.col.f32.tf32.tf32.f32 "
        "{%0,%1,%2,%3}, {%4,%5,%6,%7}, {%8,%9}, {%0,%1,%2,%3};"
        : "+f"(d[0]), "+f"(d[1]), "+f"(d[2]), "+f"(d[3])
        : "r"(a[0]), "r"(a[1]), "r"(a[2]), "r"(a[3]), "r"(b[0]), "r"(b[1]));
}

// ---------------- LayerNorm ----------------
__global__ void ln_kernel(int in_id, const float* __restrict__ x_ext,
                          const float* __restrict__ g, const float* __restrict__ b,
                          int out_id) {
    const float* x = resolve_c(in_id, x_ext);
    float* out = g_ptrs[out_id];
    int row = blockIdx.x;
    int tid = threadIdx.x;
    const float4* xr = (const float4*)(x + (size_t)row * Dm);
    float4 v = xr[tid];
    float s  = v.x + v.y + v.z + v.w;
    float ss = v.x*v.x + v.y*v.y + v.z*v.z + v.w*v.w;
    #pragma unroll
    for (int o = 16; o > 0; o >>= 1) {
        s  += __shfl_xor_sync(0xffffffffu, s,  o);
        ss += __shfl_xor_sync(0xffffffffu, ss, o);
    }
    __shared__ float sh_s[8], sh_ss[8];
    int w = tid >> 5, lane = tid & 31;
    if (lane == 0) { sh_s[w] = s; sh_ss[w] = ss; }
    __syncthreads();
    s = 0.f; ss = 0.f;
    #pragma unroll
    for (int i = 0; i < 8; i++) { s += sh_s[i]; ss += sh_ss[i]; }
    float mu  = s * (1.0f / Dm);
    float var = ss * (1.0f / Dm) - mu * mu;
    float r   = rsqrtf(var + 1e-5f);
    float4 gg = ((const float4*)g)[tid];
    float4 bb = ((const float4*)b)[tid];
    float4 o4;
    o4.x = (v.x - mu) * r * gg.x + bb.x;
    o4.y = (v.y - mu) * r * gg.y + bb.y;
    o4.z = (v.z - mu) * r * gg.z + bb.z;
    o4.w = (v.w - mu) * r * gg.w + bb.w;
    ((float4*)(out + (size_t)row * Dm))[tid] = o4;
}

// ---------------- weight transpose: W[K][N] -> g_wt[N][K] ----------------
__global__ void transpose_w(const float* __restrict__ W, int K, int N) {
    __shared__ float t[32][33];
    int bx = blockIdx.x * 32;   // n
    int by = blockIdx.y * 32;   // k
    int x = threadIdx.x, y = threadIdx.y;   // 32 x 8
    #pragma unroll
    for (int j = 0; j < 4; j++)
        t[y + 8*j][x] = W[(size_t)(by + y + 8*j) * N + bx + x];
    __syncthreads();
    #pragma unroll
    for (int j = 0; j < 4; j++)
        g_wt[(size_t)(bx + y + 8*j) * K + by + x] = t[x][y + 8*j];
}

// ---------------- GELU (exact) ----------------
__device__ __forceinline__ float gelu_f(float x) {
    return 0.5f * x * (1.0f + erff(x * 0.70710678118654752f));
}

// ---------------- tf32 mma.sync GEMM ----------------
#define PAD 36

template<int EPI>
__global__ __launch_bounds__(256)
void gemm_mma(int a_id, const float* __restrict__ bias,
              int res_id, const float* __restrict__ res_ext,
              int c_id, float* __restrict__ c_ext,
              int M, int N, int K) {
    const float* A  = (const float*)g_ptrs[a_id];
    const float* Bw = g_wt;
    const float* res = (EPI == 1) ? resolve_c(res_id, res_ext) : nullptr;
    float* C = resolve_m(c_id, c_ext);

    __shared__ uint32_t As[128 * PAD];
    __shared__ uint32_t Bs[128 * PAD];

    const int tid  = threadIdx.x;
    const int wid  = tid >> 5, lane = tid & 31;
    const int row0 = blockIdx.y * 128;
    const int col0 = blockIdx.x * 128;
    const int mw   = (wid & 1) * 64;
    const int nw   = (wid >> 1) * 32;
    const int lr   = tid >> 1;
    const int lc   = (tid & 1) * 16;

    float acc[4][4][4];
    #pragma unroll
    for (int i = 0; i < 4; i++)
        #pragma unroll
        for (int j = 0; j < 4; j++)
            #pragma unroll
            for (int e = 0; e < 4; e++) acc[i][j][e] = 0.f;

    const int r4 = lane >> 2, c4 = lane & 3;

    for (int k0 = 0; k0 < K; k0 += 32) {
        const float4* pa = (const float4*)(A  + (size_t)(row0 + lr) * K + k0 + lc);
        const float4* pb = (const float4*)(Bw + (size_t)(col0 + lr) * K + k0 + lc);
        #pragma unroll
        for (int j = 0; j < 4; j++) {
            float4 va = pa[j];
            uint4 ua = { to_tf32(va.x), to_tf32(va.y), to_tf32(va.z), to_tf32(va.w) };
            *(uint4*)&As[lr * PAD + lc + 4*j] = ua;
            float4 vb = pb[j];
            uint4 ub = { to_tf32(vb.x), to_tf32(vb.y), to_tf32(vb.z), to_tf32(vb.w) };
            *(uint4*)&Bs[lr * PAD + lc + 4*j] = ub;
        }
        __syncthreads();

        #pragma unroll
        for (int ks = 0; ks < 4; ks++) {
            const int kb = ks * 8;
            uint32_t afr[4][4];
            #pragma unroll
            for (int mt = 0; mt < 4; mt++) {
                int m = mw + mt * 16;
                afr[mt][0] = As[(m + r4)     * PAD + kb + c4];
                afr[mt][1] = As[(m + r4 + 8) * PAD + kb + c4];
                afr[mt][2] = As[(m + r4)     * PAD + kb + c4 + 4];
                afr[mt][3] = As[(m + r4 + 8) * PAD + kb + c4 + 4];
            }
            uint32_t bfr[4][2];
            #pragma unroll
            for (int nt = 0; nt < 4; nt++) {
                int n = nw + nt * 8;
                bfr[nt][0] = Bs[(n + r4) * PAD + kb + c4];
                bfr[nt][1] = Bs[(n + r4) * PAD + kb + c4 + 4];
            }
            #pragma unroll
            for (int mt = 0; mt < 4; mt++)
                #pragma unroll
                for (int nt = 0; nt < 4; nt++)
                    mma_tf32(acc[mt][nt], afr[mt], bfr[nt]);
        }
        __syncthreads();
    }

    #pragma unroll
    for (int mt = 0; mt < 4; mt++) {
        #pragma unroll
        for (int nt = 0; nt < 4; nt++) {
            int gm = row0 + mw + mt * 16 + r4;
            int gn = col0 + nw + nt * 8 + 2 * c4;
            float2 bi = *(const float2*)(bias + gn);
            #pragma unroll
            for (int half = 0; half < 2; half++) {
                int rr = gm + half * 8;
                float2 v;
                v.x = acc[mt][nt][half*2 + 0] + bi.x;
                v.y = acc[mt][nt][half*2 + 1] + bi.y;
                if (EPI == 1) {
                    float2 r2 = *(const float2*)(res + (size_t)rr * N + gn);
                    v.x += r2.x; v.y += r2.y;
                }
                if (EPI == 2) { v.x = gelu_f(v.x); v.y = gelu_f(v.y); }
                *(float2*)(C + (size_t)rr * N + gn) = v;
            }
        }
    }
}

// ---------------- tensor-core flash attention (tf32 mma) ----------------
// CTA: 64 query rows, 128 threads (4 warps x 16 rows). K-tile = 64 keys.
// Ks[key][d] (B-operand for S = Q K^T), Vt[d][key] (B-operand for P V).
#define APAD 68

__global__ __launch_bounds__(128)
void attn_mma() {
    __shared__ uint32_t Ks[64 * APAD];
    __shared__ uint32_t Vt[64 * APAD];

    const int tid  = threadIdx.x;
    const int wid  = tid >> 5, lane = tid & 31;
    const int r4   = lane >> 2, c4 = lane & 3;
    const int bh   = blockIdx.y;
    const int b    = bh / HEADS, h = bh % HEADS;
    const int q0   = blockIdx.x * 64;
    const float* base = g_qkv + (size_t)b * SEQ * (3 * Dm);
    const int ldq  = 3 * Dm;

    // ---- stage Q (x0.125, exact in tf32) into Ks, then extract A-fragments ----
    {
        int row = tid >> 1, half = tid & 1;
        const float4* src = (const float4*)(base + (size_t)(q0 + row) * ldq + h * HDIM + half * 32);
        uint32_t* dst = &Ks[row * APAD + half * 32];
        #pragma unroll
        for (int j = 0; j < 8; j++) {
            float4 v = src[j];
            dst[4*j+0] = to_tf32(v.x * 0.125f);
            dst[4*j+1] = to_tf32(v.y * 0.125f);
            dst[4*j+2] = to_tf32(v.z * 0.125f);
            dst[4*j+3] = to_tf32(v.w * 0.125f);
        }
    }
    __syncthreads();
    uint32_t qfr[8][4];
    {
        int m0 = wid * 16;
        #pragma unroll
        for (int ks = 0; ks < 8; ks++) {
            int kb = ks * 8;
            qfr[ks][0] = Ks[(m0 + r4)     * APAD + kb + c4];
            qfr[ks][1] = Ks[(m0 + r4 + 8) * APAD + kb + c4];
            qfr[ks][2] = Ks[(m0 + r4)     * APAD + kb + c4 + 4];
            qfr[ks][3] = Ks[(m0 + r4 + 8) * APAD + kb + c4 + 4];
        }
    }

    float accO[8][4];
    #pragma unroll
    for (int nt = 0; nt < 8; nt++)
        #pragma unroll
        for (int e = 0; e < 4; e++) accO[nt][e] = 0.f;
    float m_lo = -1e30f, m_hi = -1e30f, l_lo = 0.f, l_hi = 0.f;

    const int  srcA = (r4 << 2) | (c4 >> 1);
    const int  srcB = srcA + 2;
    const bool odd  = (c4 & 1);

    for (int kt = 0; kt < SEQ; kt += 64) {
        __syncthreads();   // previous tile fully consumed
        // ---- load K tile -> Ks[key][d], V tile -> Vt[d][key] ----
        {
            int row = tid >> 1, half = tid & 1;
            const float* krow = base + (size_t)(kt + row) * ldq + Dm + h * HDIM + half * 32;
            const float4* ksrc = (const float4*)krow;
            uint32_t* kdst = &Ks[row * APAD + half * 32];
            #pragma unroll
            for (int j = 0; j < 8; j++) {
                float4 v = ksrc[j];
                kdst[4*j+0] = to_tf32(v.x); kdst[4*j+1] = to_tf32(v.y);
                kdst[4*j+2] = to_tf32(v.z); kdst[4*j+3] = to_tf32(v.w);
            }
            const float4* vsrc = (const float4*)(krow + Dm);
            #pragma unroll
            for (int j = 0; j < 8; j++) {
                float4 v = vsrc[j];
                int d = half * 32 + 4 * j;
                Vt[(d+0) * APAD + row] = to_tf32(v.x);
                Vt[(d+1) * APAD + row] = to_tf32(v.y);
                Vt[(d+2) * APAD + row] = to_tf32(v.z);
                Vt[(d+3) * APAD + row] = to_tf32(v.w);
            }
        }
        __syncthreads();

        // ---- S = Q K^T  (warp: 16 rows x 64 keys) ----
        float accS[8][4];
        #pragma unroll
        for (int nt = 0; nt < 8; nt++)
            #pragma unroll
            for (int e = 0; e < 4; e++) accS[nt][e] = 0.f;
        #pragma unroll
        for (int ks = 0; ks < 8; ks++) {
            int kb = ks * 8;
            #pragma unroll
            for (int nt = 0; nt < 8; nt++) {
                uint32_t bfr[2];
                bfr[0] = Ks[(nt*8 + r4) * APAD + kb + c4];
                bfr[1] = Ks[(nt*8 + r4) * APAD + kb + c4 + 4];
                mma_tf32(accS[nt], qfr[ks], bfr);
            }
        }

        // ---- online softmax ----
        float rmax_lo = -1e30f, rmax_hi = -1e30f;
        #pragma unroll
        for (int nt = 0; nt < 8; nt++) {
            rmax_lo = fmaxf(rmax_lo, fmaxf(accS[nt][0], accS[nt][1]));
            rmax_hi = fmaxf(rmax_hi, fmaxf(accS[nt][2], accS[nt][3]));
        }
        rmax_lo = fmaxf(rmax_lo, __shfl_xor_sync(0xffffffffu, rmax_lo, 1));
        rmax_lo = fmaxf(rmax_lo, __shfl_xor_sync(0xffffffffu, rmax_lo, 2));
        rmax_hi = fmaxf(rmax_hi, __shfl_xor_sync(0xffffffffu, rmax_hi, 1));
        rmax_hi = fmaxf(rmax_hi, __shfl_xor_sync(0xffffffffu, rmax_hi, 2));

        float mn_lo = fmaxf(m_lo, rmax_lo);
        float mn_hi = fmaxf(m_hi, rmax_hi);
        float corr_lo = __expf(m_lo - mn_lo);
        float corr_hi = __expf(m_hi - mn_hi);
        m_lo = mn_lo; m_hi = mn_hi;

        float rs_lo = 0.f, rs_hi = 0.f;
        uint32_t pb[8][4];
        #pragma unroll
        for (int nt = 0; nt < 8; nt++) {
            float p0 = __expf(accS[nt][0] - m_lo);
            float p1 = __expf(accS[nt][1] - m_lo);
            float p2 = __expf(accS[nt][2] - m_hi);
            float p3 = __expf(accS[nt][3] - m_hi);
            rs_lo += p0 + p1; rs_hi += p2 + p3;
            pb[nt][0] = to_tf32(p0); pb[nt][1] = to_tf32(p1);
            pb[nt][2] = to_tf32(p2); pb[nt][3] = to_tf32(p3);
        }
        rs_lo += __shfl_xor_sync(0xffffffffu, rs_lo, 1);
        rs_lo += __shfl_xor_sync(0xffffffffu, rs_lo, 2);
        rs_hi += __shfl_xor_sync(0xffffffffu, rs_hi, 1);
        rs_hi += __shfl_xor_sync(0xffffffffu, rs_hi, 2);
        l_lo = l_lo * corr_lo + rs_lo;
        l_hi = l_hi * corr_hi + rs_hi;

        #pragma unroll
        for (int nt = 0; nt < 8; nt++) {
            accO[nt][0] *= corr_lo; accO[nt][1] *= corr_lo;
            accO[nt][2] *= corr_hi; accO[nt][3] *= corr_hi;
        }

        // ---- O += P V : remap P from C-layout to A-layout via shfl ----
        #pragma unroll
        for (int ks = 0; ks < 8; ks++) {
            uint32_t a[4], t0, t1;
            t0 = __shfl_sync(0xffffffffu, pb[ks][0], srcA);
            t1 = __shfl_sync(0xffffffffu, pb[ks][1], srcA);
            a[0] = odd ? t1 : t0;
            t0 = __shfl_sync(0xffffffffu, pb[ks][2], srcA);
            t1 = __shfl_sync(0xffffffffu, pb[ks][3], srcA);
            a[1] = odd ? t1 : t0;
            t0 = __shfl_sync(0xffffffffu, pb[ks][0], srcB);
            t1 = __shfl_sync(0xffffffffu, pb[ks][1], srcB);
            a[2] = odd ? t1 : t0;
            t0 = __shfl_sync(0xffffffffu, pb[ks][2], srcB);
            t1 = __shfl_sync(0xffffffffu, pb[ks][3], srcB);
            a[3] = odd ? t1 : t0;
            int kb = ks * 8;
            #pragma unroll
            for (int nt = 0; nt < 8; nt++) {
                uint32_t bfr[2];
                bfr[0] = Vt[(nt*8 + r4) * APAD + kb + c4];
                bfr[1] = Vt[(nt*8 + r4) * APAD + kb + c4 + 4];
                mma_tf32(accO[nt], a, bfr);
            }
        }
    }

    // ---- write O ----
    float il_lo = 1.0f / l_lo, il_hi = 1.0f / l_hi;
    int row_lo = q0 + wid * 16 + r4;
    float* o_lo = g_o + (size_t)(b * SEQ + row_lo) * Dm + h * HDIM;
    float* o_hi = o_lo + 8 * Dm;
    #pragma unroll
    for (int nt = 0; nt < 8; nt++) {
        float2 v;
        v.x = accO[nt][0] * il_lo; v.y = accO[nt][1] * il_lo;
        *(float2*)(o_lo + nt * 8 + 2 * c4) = v;
        v.x = accO[nt][2] * il_hi; v.y = accO[nt][3] * il_hi;
        *(float2*)(o_hi + nt * 8 + 2 * c4) = v;
    }
}

// ---------------- launch ----------------
// Buffer ids: 0=g_h 1=g_qkv 2=g_o 3=g_x1 4=g_m 5=g_ma 6=g_wt ; -1 = external
extern "C" void kernel_launch(void* const* d_in, const int* in_sizes, int n_in,
                              void* d_out, int out_size) {
    const float* x      = (const float*)d_in[0];
    const float* ln1_g  = (const float*)d_in[1];
    const float* ln1_b  = (const float*)d_in[2];
    const float* lnm_g  = (const float*)d_in[3];
    const float* lnm_b  = (const float*)d_in[4];
    const float* qkv_w  = (const float*)d_in[5];
    const float* qkv_b  = (const float*)d_in[6];
    const float* proj_w = (const float*)d_in[7];
    const float* proj_b = (const float*)d_in[8];
    const float* fc1_w  = (const float*)d_in[9];
    const float* fc1_b  = (const float*)d_in[10];
    const float* fc2_w  = (const float*)d_in[11];
    const float* fc2_b  = (const float*)d_in[12];
    float* out = (float*)d_out;

    // 1. LN1: g_h = LN(x)
    ln_kernel<<<ROWS, 256>>>(-1, x, ln1_g, ln1_b, 0);
    // 2. QKV: g_qkv = g_h @ qkv_w + qkv_b
    transpose_w<<<dim3(3 * Dm / 32, Dm / 32), dim3(32, 8)>>>(qkv_w, Dm, 3 * Dm);
    gemm_mma<0><<<dim3(3 * Dm / 128, ROWS / 128), 256>>>(
        0, qkv_b, -1, nullptr, 1, nullptr, ROWS, 3 * Dm, Dm);
    // 3. attention (tensor-core flash)
    attn_mma<<<dim3(SEQ / 64, BATCH * HEADS), 128>>>();
    // 4. g_x1 = x + g_o @ proj_w + proj_b
    transpose_w<<<dim3(Dm / 32, Dm / 32), dim3(32, 8)>>>(proj_w, Dm, Dm);
    gemm_mma<1><<<dim3(Dm / 128, ROWS / 128), 256>>>(
        2, proj_b, -1, x, 3, nullptr, ROWS, Dm, Dm);
    // 5. LNm: g_m = LN(g_x1)
    ln_kernel<<<ROWS, 256>>>(3, nullptr, lnm_g, lnm_b, 4);
    // 6. g_ma = gelu(g_m @ fc1_w + fc1_b)
    transpose_w<<<dim3(MLPD / 32, Dm / 32), dim3(32, 8)>>>(fc1_w, Dm, MLPD);
    gemm_mma<2><<<dim3(MLPD / 128, ROWS / 128), 256>>>(
        4, fc1_b, -1, nullptr, 5, nullptr, ROWS, MLPD, Dm);
    // 7. out = g_x1 + g_ma @ fc2_w + fc2_b
    transpose_w<<<dim3(Dm / 32, MLPD / 32), dim3(32, 8)>>>(fc2_w, MLPD, Dm);
    gemm_mma<1><<<dim3(Dm / 128, ROWS / 128), 256>>>(
        5, fc2_b, 3, nullptr, -1, out, ROWS, Dm, MLPD);
}